// round 6
// baseline (speedup 1.0000x reference)
#include <cuda_runtime.h>

#define LBL 32
#define WPB 8

typedef unsigned long long u64;

// Static device scratch (allocation-free). Distinct buffer per phase:
// every inter-phase address is written once, read once per launch.
__device__ __align__(16) float g_P1[16384 * LBL];
__device__ __align__(16) float g_Mv1[16384];
__device__ __align__(16) float g_P2[2048 * LBL];
__device__ __align__(16) float g_Mv2[2048];
__device__ __align__(16) float g_P3[256 * LBL];
__device__ __align__(16) float g_Mv3[256];
__device__ __align__(16) float g_P4[32 * LBL];
__device__ __align__(16) float g_Mv4[32];

// Grid barrier state (re-entrant across graph replays: count returns to 0,
// phase is monotone and sampled at kernel start).
__device__ unsigned g_bar_count = 0;
__device__ unsigned g_bar_phase = 0;

__device__ __forceinline__ void grid_barrier(unsigned nblocks, unsigned& myphase) {
    __syncthreads();
    if (threadIdx.x == 0) {
        __threadfence();
        unsigned arr = atomicAdd(&g_bar_count, 1u);
        if (arr == nblocks - 1u) {
            g_bar_count = 0;
            __threadfence();
            atomicAdd(&g_bar_phase, 1u);
        } else {
            while (*(volatile unsigned*)&g_bar_phase == myphase)
                __nanosleep(64);
        }
    }
    __syncthreads();
    myphase++;
}

__device__ __forceinline__ u64 pack2(float a, float b) {
    u64 r; asm("mov.b64 %0, {%1,%2};" : "=l"(r) : "f"(a), "f"(b)); return r;
}

// expT row of this lane, packed as 16 x (f32,f32) in b64 registers.
__device__ __forceinline__ void load_expT2(u64 rT2[16],
                                           const float* __restrict__ trans,
                                           int lane) {
    #pragma unroll
    for (int j = 0; j < 8; j++) {
        float4 v = ((const float4*)trans)[lane * 8 + j];
        rT2[2 * j]     = pack2(__expf(v.x), __expf(v.y));
        rT2[2 * j + 1] = pack2(__expf(v.z), __expf(v.w));
    }
}

// dot(expT[lane,:], p[0..31]) with packed f32x2 FMAs (16 FFMA2, 8 LD.128).
__device__ __forceinline__ float dot2(const float* __restrict__ prow,
                                      const u64 rT2[16]) {
    const ulonglong2* p2 = (const ulonglong2*)prow;
    u64 acc0 = 0ull, acc1 = 0ull;
    #pragma unroll
    for (int j = 0; j < 8; j++) {
        ulonglong2 v = p2[j];
        asm("fma.rn.f32x2 %0, %1, %2, %0;" : "+l"(acc0) : "l"(rT2[2 * j]),     "l"(v.x));
        asm("fma.rn.f32x2 %0, %1, %2, %0;" : "+l"(acc1) : "l"(rT2[2 * j + 1]), "l"(v.y));
    }
    float a, b, c, d;
    asm("mov.b64 {%0,%1}, %2;" : "=f"(a), "=f"(b) : "l"(acc0));
    asm("mov.b64 {%0,%1}, %2;" : "=f"(c), "=f"(d) : "l"(acc1));
    return (a + b) + (c + d);
}

__device__ __forceinline__ float wmax(float v) {
    #pragma unroll
    for (int o = 16; o; o >>= 1)
        v = fmaxf(v, __shfl_xor_sync(0xffffffffu, v, o));
    return v;
}

// Consume two pre-exponentiated child rows:
//   r[l] = em[l] + ML + MR + log( dot(expT[l,:],pL) * dot(expT[l,:],pR) )
__device__ __forceinline__ float consume(const float* __restrict__ pL,
                                         float ML, float MR, float emv,
                                         const u64 rT2[16]) {
    float dL = dot2(pL, rT2);
    float dR = dot2(pL + LBL, rT2);
    return emv + ML + MR + __logf(dL * dR);
}

// Produce (p, M) form of a result row (warp-collective).
__device__ __forceinline__ void produce(float r, int lane,
                                        float* __restrict__ prow,
                                        float* __restrict__ Mslot) {
    float m = wmax(r);
    prow[lane] = __expf(r - m);
    if (lane == 0) *Mslot = m;
}

// ---------------------------------------------------------------------------
// Persistent kernel: all 17 levels in one launch; grid barrier between
// fused-3 groups. Slab = 32 nodes at level V -> 16 -> 8 through shared mem.
// All stored rows use (p, M) form; leaves (raw) use the staging path.
// ---------------------------------------------------------------------------
__global__ void __launch_bounds__(WPB * 32, 3)
persistent_kernel(const float* __restrict__ emissions,
                  const float* __restrict__ trans,
                  float* __restrict__ d_out,
                  int n_leaves)
{
    __shared__ __align__(16) float s1[32 * LBL];
    __shared__ __align__(16) float s2[16 * LBL];
    __shared__ float sM1[32];
    __shared__ float sM2[16];
    __shared__ __align__(16) float stg[WPB][2 * LBL];

    int lane = threadIdx.x & 31;
    int w    = threadIdx.x >> 5;
    unsigned nblocks = gridDim.x;
    unsigned myphase = *(volatile unsigned*)&g_bar_phase;

    u64 rT2[16];
    load_expT2(rT2, trans, lane);

    float* Pout[4] = { g_P1, g_P2, g_P3, g_P4 };
    float* Mout[4] = { g_Mv1, g_Mv2, g_Mv3, g_Mv4 };

    const float* leaves = emissions + (size_t)(n_leaves - 1) * LBL;
    const float* childP = nullptr;
    const float* childM = nullptr;

    int V = n_leaves / 2;
    int gi = 0;
    while (V >= 128) {
        float* oP = Pout[gi];
        float* oM = Mout[gi];
        const float* em1 = emissions + (size_t)(V - 1) * LBL;
        const float* em2 = emissions + (size_t)(V / 2 - 1) * LBL;
        const float* em3 = emissions + (size_t)(V / 4 - 1) * LBL;
        int nslabs = V / 32;

        for (int s = blockIdx.x; s < nslabs; s += nblocks) {
            // ---- Stage 1: 32 nodes at level V.
            if (gi == 0) {
                // Raw leaf children: coalesced loads + per-child ladder/exp,
                // depth-1 prefetch of next node's loads.
                int g0 = s * 32 + w;
                float lv = leaves[(size_t)(2 * g0) * LBL + lane];
                float rv = leaves[(size_t)(2 * g0) * LBL + LBL + lane];
                float ev = em1[(size_t)g0 * LBL + lane];
                #pragma unroll
                for (int i = 0; i < 4; i++) {
                    float lv2, rv2, ev2;
                    if (i < 3) {
                        int g = s * 32 + (i + 1) * WPB + w;
                        lv2 = leaves[(size_t)(2 * g) * LBL + lane];
                        rv2 = leaves[(size_t)(2 * g) * LBL + LBL + lane];
                        ev2 = em1[(size_t)g * LBL + lane];
                    }
                    float ml = lv, mr = rv;
                    #pragma unroll
                    for (int o = 16; o; o >>= 1) {
                        ml = fmaxf(ml, __shfl_xor_sync(0xffffffffu, ml, o));
                        mr = fmaxf(mr, __shfl_xor_sync(0xffffffffu, mr, o));
                    }
                    stg[w][lane]       = __expf(lv - ml);
                    stg[w][LBL + lane] = __expf(rv - mr);
                    __syncwarp();
                    float r = ev + ml + mr +
                              __logf(dot2(stg[w], rT2) * dot2(stg[w] + LBL, rT2));
                    __syncwarp();
                    int n = i * WPB + w;
                    produce(r, lane, s1 + n * LBL, sM1 + n);
                    lv = lv2; rv = rv2; ev = ev2;
                }
            } else {
                // Children already in (p, M) form in global memory.
                #pragma unroll
                for (int i = 0; i < 4; i++) {
                    int n = i * WPB + w;
                    int g = s * 32 + n;
                    float emv = em1[(size_t)g * LBL + lane];
                    const float* pL = childP + (size_t)(2 * g) * LBL;
                    float r = consume(pL, childM[2 * g], childM[2 * g + 1],
                                      emv, rT2);
                    produce(r, lane, s1 + n * LBL, sM1 + n);
                }
            }
            __syncthreads();

            // ---- Stage 2: 16 nodes at level V/2, children in s1.
            #pragma unroll
            for (int i = 0; i < 2; i++) {
                int n = i * WPB + w;
                float emv = em2[(size_t)(s * 16 + n) * LBL + lane];
                float r = consume(s1 + 2 * n * LBL, sM1[2 * n], sM1[2 * n + 1],
                                  emv, rT2);
                produce(r, lane, s2 + n * LBL, sM2 + n);
            }
            __syncthreads();

            // ---- Stage 3: 8 nodes at level V/4, children in s2 -> global.
            {
                int n = w;
                float emv = em3[(size_t)(s * 8 + n) * LBL + lane];
                float r = consume(s2 + 2 * n * LBL, sM2[2 * n], sM2[2 * n + 1],
                                  emv, rT2);
                produce(r, lane, oP + (size_t)(s * 8 + n) * LBL, oM + (s * 8 + n));
            }
            __syncthreads();   // s1/s2/sM reuse safety for next slab
        }

        grid_barrier(nblocks, myphase);
        childP = oP;
        childM = oM;
        V >>= 3;
        gi++;
    }

    // ---- Tail: levels V..1 (V=16 for 131072 leaves), block 0 only.
    if (blockIdx.x == 0) {
        const float* cP = childP;
        const float* cM = childM;
        float* oP = s1; float* oM = sM1;
        for (int v = V; v >= 1; v >>= 1) {
            const float* em = emissions + (size_t)(v - 1) * LBL;
            for (int n = w; n < v; n += WPB) {
                float emv = em[(size_t)n * LBL + lane];
                float r = consume(cP + (size_t)(2 * n) * LBL,
                                  cM[2 * n], cM[2 * n + 1], emv, rT2);
                if (v > 1) produce(r, lane, oP + n * LBL, oM + n);
                else       d_out[lane] = r;
            }
            __syncthreads();
            cP = oP; cM = oM;
            if (oP == s1) { oP = s2; oM = sM2; }
            else          { oP = s1; oM = sM1; }
        }
    }
}

// ---------------------------------------------------------------------------
// One graph node. Grid sized so ALL blocks are simultaneously resident
// (required by the software grid barrier).
// ---------------------------------------------------------------------------
extern "C" void kernel_launch(void* const* d_in, const int* in_sizes, int n_in,
                              void* d_out, int out_size)
{
    const float* emissions = (const float*)d_in[0];
    const float* trans     = (const float*)d_in[1];
    float* out = (float*)d_out;

    int n_nodes  = in_sizes[0] / LBL;
    int n_leaves = (n_nodes + 1) / 2;

    static int grid = 0;
    if (grid == 0) {
        int dev = 0, sms = 0, perSM = 0;
        cudaGetDevice(&dev);
        cudaDeviceGetAttribute(&sms, cudaDevAttrMultiProcessorCount, dev);
        cudaOccupancyMaxActiveBlocksPerMultiprocessor(
            &perSM, persistent_kernel, WPB * 32, 0);
        if (perSM < 1) perSM = 1;
        grid = sms * perSM;
        int maxSlabs = (n_leaves / 2) / 32;
        if (grid > maxSlabs) grid = maxSlabs;
        if (grid < 1) grid = 1;
    }

    persistent_kernel<<<grid, WPB * 32>>>(emissions, trans, out, n_leaves);
}

// round 7
// speedup vs baseline: 1.2426x; 1.2426x over previous
#include <cuda_runtime.h>

#define LBL 32
#define WPB 8   // warps per block

typedef unsigned long long u64;

// Static device scratch (allocation-free per harness rules).
// Distinct buffer per phase -> every inter-phase address is written once,
// read once per launch (no cross-SM L1 staleness; L1 flushed at launch).
__device__ __align__(16) float g_A[16384 * LBL];
__device__ __align__(16) float g_B[2048 * LBL];
__device__ __align__(16) float g_C[256 * LBL];
__device__ __align__(16) float g_D[32 * LBL];

// Grid barrier state (re-entrant across graph replays: count returns to 0,
// phase is monotone and sampled at kernel start).
__device__ unsigned g_bar_count = 0;
__device__ unsigned g_bar_phase = 0;

__device__ __forceinline__ void grid_barrier(unsigned nblocks, unsigned& myphase) {
    __syncthreads();
    if (threadIdx.x == 0) {
        __threadfence();
        unsigned arr = atomicAdd(&g_bar_count, 1u);
        if (arr == nblocks - 1u) {
            g_bar_count = 0;          // all arrived; safe to reset
            __threadfence();
            atomicAdd(&g_bar_phase, 1u);   // release
        } else {
            while (*(volatile unsigned*)&g_bar_phase == myphase)
                __nanosleep(64);
        }
    }
    __syncthreads();
    myphase++;
}

__device__ __forceinline__ u64 pack2(float a, float b) {
    u64 r; asm("mov.b64 %0, {%1,%2};" : "=l"(r) : "f"(a), "f"(b)); return r;
}

// expT row of this lane, packed as 16 x (f32,f32) in b64 registers
// (same 32-reg footprint as the scalar version).
__device__ __forceinline__ void load_expT2(u64 rT2[16],
                                           const float* __restrict__ trans,
                                           int lane) {
    #pragma unroll
    for (int j = 0; j < 8; j++) {
        float4 v = ((const float4*)trans)[lane * 8 + j];
        rT2[2 * j]     = pack2(__expf(v.x), __expf(v.y));
        rT2[2 * j + 1] = pack2(__expf(v.z), __expf(v.w));
    }
}

// dot(expT[lane,:], prow[0..31]) from 16B-aligned shared memory:
// 8 broadcast LDS.128 + 16 packed FFMA2 (two independent chains).
__device__ __forceinline__ float dot2s(const float* __restrict__ prow,
                                       const u64 rT2[16]) {
    const ulonglong2* p2 = (const ulonglong2*)prow;
    u64 acc0 = 0ull, acc1 = 0ull;
    #pragma unroll
    for (int j = 0; j < 8; j++) {
        ulonglong2 v = p2[j];
        asm("fma.rn.f32x2 %0, %1, %2, %0;" : "+l"(acc0) : "l"(rT2[2 * j]),     "l"(v.x));
        asm("fma.rn.f32x2 %0, %1, %2, %0;" : "+l"(acc1) : "l"(rT2[2 * j + 1]), "l"(v.y));
    }
    float a, b, c, d;
    asm("mov.b64 {%0,%1}, %2;" : "=f"(a), "=f"(b) : "l"(acc0));
    asm("mov.b64 {%0,%1}, %2;" : "=f"(c), "=f"(d) : "l"(acc1));
    return (a + b) + (c + d);
}

// ---------------------------------------------------------------------------
// Per-node compute with PER-CHILD stabilization:
//   out[l] = em[l] + ml + mr + log( dot(expT[l,:],eL) * dot(expT[l,:],eR) )
// Each dot is in (1, ~1600], so the fused log is safe.
// Inputs lv/rv/emv are preloaded by the caller (enables prefetch).
// ---------------------------------------------------------------------------
__device__ __forceinline__ float node_core(
    float lv, float rv, float emv, int lane,
    float* __restrict__ s_el, float* __restrict__ s_er,
    const u64 rT2[16])
{
    float ml = lv, mr = rv;
    #pragma unroll
    for (int o = 16; o; o >>= 1) {
        ml = fmaxf(ml, __shfl_xor_sync(0xffffffffu, ml, o));
        mr = fmaxf(mr, __shfl_xor_sync(0xffffffffu, mr, o));
    }

    s_el[lane] = __expf(lv - ml);
    s_er[lane] = __expf(rv - mr);
    __syncwarp();

    float res = emv + ml + mr + __logf(dot2s(s_el, rT2) * dot2s(s_er, rT2));
    __syncwarp();   // protect shared staging before next call's writes
    return res;
}

// ---------------------------------------------------------------------------
// Persistent kernel: all levels in one launch, grid barrier between fused-3
// groups. Slab = 32 nodes at level V -> 16 -> 8 through shared memory.
// ---------------------------------------------------------------------------
__global__ void __launch_bounds__(WPB * 32, 3)
persistent_kernel(const float* __restrict__ emissions,
                  const float* __restrict__ trans,
                  float* __restrict__ d_out,
                  int n_leaves)
{
    __shared__ __align__(16) float s1[32 * LBL];
    __shared__ __align__(16) float s2[16 * LBL];
    __shared__ __align__(16) float stg[WPB][2 * LBL];

    int lane = threadIdx.x & 31;
    int w    = threadIdx.x >> 5;
    unsigned nblocks = gridDim.x;

    // Sample barrier phase before any barrier can release (all blocks are
    // resident and must arrive before release, so this read is race-free).
    unsigned myphase = *(volatile unsigned*)&g_bar_phase;

    u64 rT2[16];
    load_expT2(rT2, trans, lane);

    float* bufs[4] = { g_A, g_B, g_C, g_D };
    const float* child = emissions + (size_t)(n_leaves - 1) * LBL;  // leaves

    int V = n_leaves / 2;
    int bi = 0;
    while (V >= 128) {
        float* out = bufs[bi++];
        const float* em1 = emissions + (size_t)(V - 1) * LBL;
        const float* em2 = emissions + (size_t)(V / 2 - 1) * LBL;
        const float* em3 = emissions + (size_t)(V / 4 - 1) * LBL;
        int nslabs = V / 32;

        for (int s = blockIdx.x; s < nslabs; s += nblocks) {
            // ---- Stage 1: 32 nodes at level V, children from global,
            //      depth-1 prefetch of the next node's loads.
            int g0 = s * 32 + w;             // i = 0
            float lv = child[(size_t)(2 * g0) * LBL + lane];
            float rv = child[(size_t)(2 * g0) * LBL + LBL + lane];
            float ev = em1[(size_t)g0 * LBL + lane];
            #pragma unroll
            for (int i = 0; i < 4; i++) {
                float lv2, rv2, ev2;
                if (i < 3) {
                    int g = s * 32 + (i + 1) * WPB + w;
                    lv2 = child[(size_t)(2 * g) * LBL + lane];
                    rv2 = child[(size_t)(2 * g) * LBL + LBL + lane];
                    ev2 = em1[(size_t)g * LBL + lane];
                }
                float r = node_core(lv, rv, ev, lane, stg[w], stg[w] + LBL, rT2);
                s1[(i * WPB + w) * LBL + lane] = r;
                lv = lv2; rv = rv2; ev = ev2;
            }
            __syncthreads();

            // ---- Stage 2: 16 nodes at level V/2, children in s1.
            #pragma unroll
            for (int i = 0; i < 2; i++) {
                int n = i * WPB + w;
                float lvs = s1[2 * n * LBL + lane];
                float rvs = s1[2 * n * LBL + LBL + lane];
                float evs = em2[(size_t)(s * 16 + n) * LBL + lane];
                float r = node_core(lvs, rvs, evs, lane, stg[w], stg[w] + LBL, rT2);
                s2[n * LBL + lane] = r;
            }
            __syncthreads();

            // ---- Stage 3: 8 nodes at level V/4, children in s2 -> global.
            {
                int n = w;
                float lvs = s2[2 * n * LBL + lane];
                float rvs = s2[2 * n * LBL + LBL + lane];
                float evs = em3[(size_t)(s * 8 + n) * LBL + lane];
                float r = node_core(lvs, rvs, evs, lane, stg[w], stg[w] + LBL, rT2);
                out[(size_t)(s * 8 + n) * LBL + lane] = r;
            }
            __syncthreads();   // s1/s2 reuse safety for next slab
        }

        grid_barrier(nblocks, myphase);
        child = out;
        V >>= 3;
    }

    // ---- Tail: remaining levels (V=16..1 for n_leaves=131072), block 0 only.
    if (blockIdx.x == 0) {
        const float* c = child;
        float* o = s1;
        for (int v = V; v >= 1; v >>= 1) {
            const float* em = emissions + (size_t)(v - 1) * LBL;
            for (int n = w; n < v; n += WPB) {
                float lvs = c[(size_t)(2 * n) * LBL + lane];
                float rvs = c[(size_t)(2 * n) * LBL + LBL + lane];
                float evs = em[(size_t)n * LBL + lane];
                float r = node_core(lvs, rvs, evs, lane, stg[w], stg[w] + LBL, rT2);
                if (v > 1) o[n * LBL + lane] = r;
                else       d_out[lane] = r;
            }
            __syncthreads();
            c = o;
            o = (o == s1) ? s2 : s1;   // v<=16 fits in s2 (16 rows)
        }
    }
}

// ---------------------------------------------------------------------------
// One graph node. Grid sized so ALL blocks are simultaneously resident
// (required by the software grid barrier).
// ---------------------------------------------------------------------------
extern "C" void kernel_launch(void* const* d_in, const int* in_sizes, int n_in,
                              void* d_out, int out_size)
{
    const float* emissions = (const float*)d_in[0];
    const float* trans     = (const float*)d_in[1];
    float* out = (float*)d_out;

    int n_nodes  = in_sizes[0] / LBL;
    int n_leaves = (n_nodes + 1) / 2;

    static int grid = 0;
    if (grid == 0) {
        int dev = 0, sms = 0, perSM = 0;
        cudaGetDevice(&dev);
        cudaDeviceGetAttribute(&sms, cudaDevAttrMultiProcessorCount, dev);
        cudaOccupancyMaxActiveBlocksPerMultiprocessor(
            &perSM, persistent_kernel, WPB * 32, 0);
        if (perSM < 1) perSM = 1;
        grid = sms * perSM;
        int maxSlabs = (n_leaves / 2) / 32;
        if (grid > maxSlabs) grid = maxSlabs;
        if (grid < 1) grid = 1;
    }

    persistent_kernel<<<grid, WPB * 32>>>(emissions, trans, out, n_leaves);
}

// round 8
// speedup vs baseline: 1.2493x; 1.0054x over previous
#include <cuda_runtime.h>

#define LBL 32
#define WPB 8   // warps per block

typedef unsigned long long u64;

// Static device scratch (allocation-free per harness rules).
// Distinct buffer per phase -> every inter-phase address is written once,
// read once per launch (no cross-SM L1 staleness; L1 flushed at launch).
__device__ __align__(16) float g_A[16384 * LBL];
__device__ __align__(16) float g_B[2048 * LBL];
__device__ __align__(16) float g_C[256 * LBL];
__device__ __align__(16) float g_D[32 * LBL];

// Grid barrier state (re-entrant across graph replays).
__device__ unsigned g_bar_count = 0;
__device__ unsigned g_bar_phase = 0;

__device__ __forceinline__ void grid_barrier(unsigned nblocks, unsigned& myphase) {
    __syncthreads();
    if (threadIdx.x == 0) {
        __threadfence();
        unsigned arr = atomicAdd(&g_bar_count, 1u);
        if (arr == nblocks - 1u) {
            g_bar_count = 0;
            __threadfence();
            atomicAdd(&g_bar_phase, 1u);
        } else {
            while (*(volatile unsigned*)&g_bar_phase == myphase)
                __nanosleep(64);
        }
    }
    __syncthreads();
    myphase++;
}

__device__ __forceinline__ u64 pack2(float a, float b) {
    u64 r; asm("mov.b64 %0, {%1,%2};" : "=l"(r) : "f"(a), "f"(b)); return r;
}

// expT row of this lane, packed as 16 x (f32,f32) in b64 registers.
__device__ __forceinline__ void load_expT2(u64 rT2[16],
                                           const float* __restrict__ trans,
                                           int lane) {
    #pragma unroll
    for (int j = 0; j < 8; j++) {
        float4 v = ((const float4*)trans)[lane * 8 + j];
        rT2[2 * j]     = pack2(__expf(v.x), __expf(v.y));
        rT2[2 * j + 1] = pack2(__expf(v.z), __expf(v.w));
    }
}

// dot(expT[lane,:], prow[0..31]) from 16B-aligned shared memory:
// 8 broadcast LDS.128 + 16 packed FFMA2 (two independent chains).
__device__ __forceinline__ float dot2s(const float* __restrict__ prow,
                                       const u64 rT2[16]) {
    const ulonglong2* p2 = (const ulonglong2*)prow;
    u64 acc0 = 0ull, acc1 = 0ull;
    #pragma unroll
    for (int j = 0; j < 8; j++) {
        ulonglong2 v = p2[j];
        asm("fma.rn.f32x2 %0, %1, %2, %0;" : "+l"(acc0) : "l"(rT2[2 * j]),     "l"(v.x));
        asm("fma.rn.f32x2 %0, %1, %2, %0;" : "+l"(acc1) : "l"(rT2[2 * j + 1]), "l"(v.y));
    }
    float a, b, c, d;
    asm("mov.b64 {%0,%1}, %2;" : "=f"(a), "=f"(b) : "l"(acc0));
    asm("mov.b64 {%0,%1}, %2;" : "=f"(c), "=f"(d) : "l"(acc1));
    return (a + b) + (c + d);
}

// ---------------------------------------------------------------------------
// Single-node compute (stage 3 / tail).
// ---------------------------------------------------------------------------
__device__ __forceinline__ float node_core(
    float lv, float rv, float emv, int lane,
    float* __restrict__ stg2,          // 2*LBL floats, per-warp
    const u64 rT2[16])
{
    float ml = lv, mr = rv;
    #pragma unroll
    for (int o = 16; o; o >>= 1) {
        ml = fmaxf(ml, __shfl_xor_sync(0xffffffffu, ml, o));
        mr = fmaxf(mr, __shfl_xor_sync(0xffffffffu, mr, o));
    }
    stg2[lane]       = __expf(lv - ml);
    stg2[LBL + lane] = __expf(rv - mr);
    __syncwarp();
    float res = emv + ml + mr + __logf(dot2s(stg2, rT2) * dot2s(stg2 + LBL, rT2));
    __syncwarp();
    return res;
}

// ---------------------------------------------------------------------------
// TWO independent nodes interleaved through the whole pipeline: the two
// ~300-cycle dependency chains (ladder -> exp -> LDS -> FFMA2 chain -> log)
// overlap within one warp. One __syncwarp pair per 2 nodes.
// ---------------------------------------------------------------------------
__device__ __forceinline__ void node_pair(
    float lv0, float rv0, float ev0,
    float lv1, float rv1, float ev1,
    int lane,
    float* __restrict__ stg4,          // 4*LBL floats, per-warp
    const u64 rT2[16],
    float& r0, float& r1)
{
    float ml0 = lv0, mr0 = rv0, ml1 = lv1, mr1 = rv1;
    #pragma unroll
    for (int o = 16; o; o >>= 1) {
        ml0 = fmaxf(ml0, __shfl_xor_sync(0xffffffffu, ml0, o));
        mr0 = fmaxf(mr0, __shfl_xor_sync(0xffffffffu, mr0, o));
        ml1 = fmaxf(ml1, __shfl_xor_sync(0xffffffffu, ml1, o));
        mr1 = fmaxf(mr1, __shfl_xor_sync(0xffffffffu, mr1, o));
    }
    stg4[lane]           = __expf(lv0 - ml0);
    stg4[LBL + lane]     = __expf(rv0 - mr0);
    stg4[2 * LBL + lane] = __expf(lv1 - ml1);
    stg4[3 * LBL + lane] = __expf(rv1 - mr1);
    __syncwarp();
    float d0 = dot2s(stg4, rT2)           * dot2s(stg4 + LBL, rT2);
    float d1 = dot2s(stg4 + 2 * LBL, rT2) * dot2s(stg4 + 3 * LBL, rT2);
    r0 = ev0 + ml0 + mr0 + __logf(d0);
    r1 = ev1 + ml1 + mr1 + __logf(d1);
    __syncwarp();
}

// ---------------------------------------------------------------------------
// Persistent kernel: all levels in one launch, grid barrier between fused-3
// groups. Slab = 32 nodes at level V -> 16 -> 8 through shared memory.
// ---------------------------------------------------------------------------
__global__ void __launch_bounds__(WPB * 32, 3)
persistent_kernel(const float* __restrict__ emissions,
                  const float* __restrict__ trans,
                  float* __restrict__ d_out,
                  int n_leaves)
{
    __shared__ __align__(16) float s1[32 * LBL];
    __shared__ __align__(16) float s2[16 * LBL];
    __shared__ __align__(16) float stg[WPB][4 * LBL];

    int lane = threadIdx.x & 31;
    int w    = threadIdx.x >> 5;
    unsigned nblocks = gridDim.x;
    unsigned myphase = *(volatile unsigned*)&g_bar_phase;

    u64 rT2[16];
    load_expT2(rT2, trans, lane);

    float* bufs[4] = { g_A, g_B, g_C, g_D };
    const float* child = emissions + (size_t)(n_leaves - 1) * LBL;  // leaves

    int V = n_leaves / 2;
    int bi = 0;
    while (V >= 128) {
        float* out = bufs[bi++];
        const float* em1 = emissions + (size_t)(V - 1) * LBL;
        const float* em2 = emissions + (size_t)(V / 2 - 1) * LBL;
        const float* em3 = emissions + (size_t)(V / 4 - 1) * LBL;
        int nslabs = V / 32;

        for (int s = blockIdx.x; s < nslabs; s += nblocks) {
            // ---- Stage 1: 32 nodes at level V, 2 pairs per warp, with
            //      depth-1 prefetch of the next pair's 6 loads.
            int n0 = 0 * WPB + w, n1 = 1 * WPB + w;   // pair 0
            float lv0 = child[(size_t)(2 * (s * 32 + n0)) * LBL + lane];
            float rv0 = child[(size_t)(2 * (s * 32 + n0)) * LBL + LBL + lane];
            float ev0 = em1[(size_t)(s * 32 + n0) * LBL + lane];
            float lv1 = child[(size_t)(2 * (s * 32 + n1)) * LBL + lane];
            float rv1 = child[(size_t)(2 * (s * 32 + n1)) * LBL + LBL + lane];
            float ev1 = em1[(size_t)(s * 32 + n1) * LBL + lane];
            #pragma unroll
            for (int t = 0; t < 2; t++) {
                float lv2, rv2, ev2, lv3, rv3, ev3;
                if (t == 0) {
                    int m0 = 2 * WPB + w, m1 = 3 * WPB + w;   // pair 1
                    lv2 = child[(size_t)(2 * (s * 32 + m0)) * LBL + lane];
                    rv2 = child[(size_t)(2 * (s * 32 + m0)) * LBL + LBL + lane];
                    ev2 = em1[(size_t)(s * 32 + m0) * LBL + lane];
                    lv3 = child[(size_t)(2 * (s * 32 + m1)) * LBL + lane];
                    rv3 = child[(size_t)(2 * (s * 32 + m1)) * LBL + LBL + lane];
                    ev3 = em1[(size_t)(s * 32 + m1) * LBL + lane];
                }
                float r0, r1;
                node_pair(lv0, rv0, ev0, lv1, rv1, ev1, lane, stg[w], rT2, r0, r1);
                int a0 = (2 * t) * WPB + w, a1 = (2 * t + 1) * WPB + w;
                s1[a0 * LBL + lane] = r0;
                s1[a1 * LBL + lane] = r1;
                lv0 = lv2; rv0 = rv2; ev0 = ev2;
                lv1 = lv3; rv1 = rv3; ev1 = ev3;
            }
            __syncthreads();

            // ---- Stage 2: 16 nodes at level V/2 (one pair per warp).
            {
                int a0 = w, a1 = WPB + w;
                float lv0s = s1[2 * a0 * LBL + lane];
                float rv0s = s1[2 * a0 * LBL + LBL + lane];
                float ev0s = em2[(size_t)(s * 16 + a0) * LBL + lane];
                float lv1s = s1[2 * a1 * LBL + lane];
                float rv1s = s1[2 * a1 * LBL + LBL + lane];
                float ev1s = em2[(size_t)(s * 16 + a1) * LBL + lane];
                float r0, r1;
                node_pair(lv0s, rv0s, ev0s, lv1s, rv1s, ev1s, lane, stg[w], rT2, r0, r1);
                s2[a0 * LBL + lane] = r0;
                s2[a1 * LBL + lane] = r1;
            }
            __syncthreads();

            // ---- Stage 3: 8 nodes at level V/4, children in s2 -> global.
            {
                int n = w;
                float lvs = s2[2 * n * LBL + lane];
                float rvs = s2[2 * n * LBL + LBL + lane];
                float evs = em3[(size_t)(s * 8 + n) * LBL + lane];
                float r = node_core(lvs, rvs, evs, lane, stg[w], rT2);
                out[(size_t)(s * 8 + n) * LBL + lane] = r;
            }
            __syncthreads();   // s1/s2 reuse safety for next slab
        }

        grid_barrier(nblocks, myphase);
        child = out;
        V >>= 3;
    }

    // ---- Tail: remaining levels (V=16..1), block 0 only.
    if (blockIdx.x == 0) {
        const float* c = child;
        float* o = s1;
        for (int v = V; v >= 1; v >>= 1) {
            const float* em = emissions + (size_t)(v - 1) * LBL;
            for (int n = w; n < v; n += WPB) {
                float lvs = c[(size_t)(2 * n) * LBL + lane];
                float rvs = c[(size_t)(2 * n) * LBL + LBL + lane];
                float evs = em[(size_t)n * LBL + lane];
                float r = node_core(lvs, rvs, evs, lane, stg[w], rT2);
                if (v > 1) o[n * LBL + lane] = r;
                else       d_out[lane] = r;
            }
            __syncthreads();
            c = o;
            o = (o == s1) ? s2 : s1;   // v<=16 fits in s2 (16 rows)
        }
    }
}

// ---------------------------------------------------------------------------
// One graph node. Grid sized so ALL blocks are simultaneously resident
// (required by the software grid barrier).
// ---------------------------------------------------------------------------
extern "C" void kernel_launch(void* const* d_in, const int* in_sizes, int n_in,
                              void* d_out, int out_size)
{
    const float* emissions = (const float*)d_in[0];
    const float* trans     = (const float*)d_in[1];
    float* out = (float*)d_out;

    int n_nodes  = in_sizes[0] / LBL;
    int n_leaves = (n_nodes + 1) / 2;

    static int grid = 0;
    if (grid == 0) {
        int dev = 0, sms = 0, perSM = 0;
        cudaGetDevice(&dev);
        cudaDeviceGetAttribute(&sms, cudaDevAttrMultiProcessorCount, dev);
        cudaOccupancyMaxActiveBlocksPerMultiprocessor(
            &perSM, persistent_kernel, WPB * 32, 0);
        if (perSM < 1) perSM = 1;
        grid = sms * perSM;
        int maxSlabs = (n_leaves / 2) / 32;
        if (grid > maxSlabs) grid = maxSlabs;
        if (grid < 1) grid = 1;
    }

    persistent_kernel<<<grid, WPB * 32>>>(emissions, trans, out, n_leaves);
}

// round 9
// speedup vs baseline: 1.3669x; 1.0941x over previous
#include <cuda_runtime.h>

#define LBL 32
#define WPB 8   // warps per block

typedef unsigned long long u64;

// Static device scratch (allocation-free per harness rules).
// Distinct buffer per phase -> every inter-phase address is written once,
// read once per launch (no cross-SM L1 staleness; L1 flushed at launch).
__device__ __align__(16) float g_A[16384 * LBL];
__device__ __align__(16) float g_B[2048 * LBL];
__device__ __align__(16) float g_C[256 * LBL];
__device__ __align__(16) float g_D[32 * LBL];

// Grid barrier state (re-entrant across graph replays).
__device__ unsigned g_bar_count = 0;
__device__ unsigned g_bar_phase = 0;

__device__ __forceinline__ void grid_barrier(unsigned nblocks, unsigned& myphase) {
    __syncthreads();
    if (threadIdx.x == 0) {
        __threadfence();
        unsigned arr = atomicAdd(&g_bar_count, 1u);
        if (arr == nblocks - 1u) {
            g_bar_count = 0;
            __threadfence();
            atomicAdd(&g_bar_phase, 1u);
        } else {
            while (*(volatile unsigned*)&g_bar_phase == myphase)
                __nanosleep(64);
        }
    }
    __syncthreads();
    myphase++;
}

// ---------------------------------------------------------------------------
// Warp max of f32 in ONE instruction: monotone map to signed int, then
// redux.sync.max.s32 (sm_80+; the f32 variant is not available on sm_103).
// key = b ^ ((b>>31) & 0x7fffffff) is order-preserving and self-inverse
// (NaN-free data).
// ---------------------------------------------------------------------------
__device__ __forceinline__ float warp_fmax1(float x) {
    int b = __float_as_int(x);
    int key = b ^ ((b >> 31) & 0x7fffffff);
    int r;
    asm("redux.sync.max.s32 %0, %1, 0xffffffff;" : "=r"(r) : "r"(key));
    return __int_as_float(r ^ ((r >> 31) & 0x7fffffff));
}

__device__ __forceinline__ u64 pack2(float a, float b) {
    u64 r; asm("mov.b64 %0, {%1,%2};" : "=l"(r) : "f"(a), "f"(b)); return r;
}

// expT row of this lane, packed as 16 x (f32,f32) in b64 registers.
__device__ __forceinline__ void load_expT2(u64 rT2[16],
                                           const float* __restrict__ trans,
                                           int lane) {
    #pragma unroll
    for (int j = 0; j < 8; j++) {
        float4 v = ((const float4*)trans)[lane * 8 + j];
        rT2[2 * j]     = pack2(__expf(v.x), __expf(v.y));
        rT2[2 * j + 1] = pack2(__expf(v.z), __expf(v.w));
    }
}

// dot(expT[lane,:], prow[0..31]) from 16B-aligned shared memory:
// 8 broadcast LDS.128 + 16 packed FFMA2 (two independent chains).
__device__ __forceinline__ float dot2s(const float* __restrict__ prow,
                                       const u64 rT2[16]) {
    const ulonglong2* p2 = (const ulonglong2*)prow;
    u64 acc0 = 0ull, acc1 = 0ull;
    #pragma unroll
    for (int j = 0; j < 8; j++) {
        ulonglong2 v = p2[j];
        asm("fma.rn.f32x2 %0, %1, %2, %0;" : "+l"(acc0) : "l"(rT2[2 * j]),     "l"(v.x));
        asm("fma.rn.f32x2 %0, %1, %2, %0;" : "+l"(acc1) : "l"(rT2[2 * j + 1]), "l"(v.y));
    }
    float a, b, c, d;
    asm("mov.b64 {%0,%1}, %2;" : "=f"(a), "=f"(b) : "l"(acc0));
    asm("mov.b64 {%0,%1}, %2;" : "=f"(c), "=f"(d) : "l"(acc1));
    return (a + b) + (c + d);
}

// ---------------------------------------------------------------------------
// Single-node compute (stage 3 / tail).
// ---------------------------------------------------------------------------
__device__ __forceinline__ float node_core(
    float lv, float rv, float emv, int lane,
    float* __restrict__ stg2,          // 2*LBL floats, per-warp
    const u64 rT2[16])
{
    float ml = warp_fmax1(lv);
    float mr = warp_fmax1(rv);
    stg2[lane]       = __expf(lv - ml);
    stg2[LBL + lane] = __expf(rv - mr);
    __syncwarp();
    float res = emv + ml + mr + __logf(dot2s(stg2, rT2) * dot2s(stg2 + LBL, rT2));
    __syncwarp();
    return res;
}

// ---------------------------------------------------------------------------
// TWO independent nodes interleaved through the whole pipeline.
// ---------------------------------------------------------------------------
__device__ __forceinline__ void node_pair(
    float lv0, float rv0, float ev0,
    float lv1, float rv1, float ev1,
    int lane,
    float* __restrict__ stg4,          // 4*LBL floats, per-warp
    const u64 rT2[16],
    float& r0, float& r1)
{
    float ml0 = warp_fmax1(lv0);
    float mr0 = warp_fmax1(rv0);
    float ml1 = warp_fmax1(lv1);
    float mr1 = warp_fmax1(rv1);
    stg4[lane]           = __expf(lv0 - ml0);
    stg4[LBL + lane]     = __expf(rv0 - mr0);
    stg4[2 * LBL + lane] = __expf(lv1 - ml1);
    stg4[3 * LBL + lane] = __expf(rv1 - mr1);
    __syncwarp();
    float d0 = dot2s(stg4, rT2)           * dot2s(stg4 + LBL, rT2);
    float d1 = dot2s(stg4 + 2 * LBL, rT2) * dot2s(stg4 + 3 * LBL, rT2);
    r0 = ev0 + ml0 + mr0 + __logf(d0);
    r1 = ev1 + ml1 + mr1 + __logf(d1);
    __syncwarp();
}

// ---------------------------------------------------------------------------
// Persistent kernel: all levels in one launch, grid barrier between fused-3
// groups. Slab = 32 nodes at level V -> 16 -> 8 through shared memory.
// ---------------------------------------------------------------------------
__global__ void __launch_bounds__(WPB * 32, 3)
persistent_kernel(const float* __restrict__ emissions,
                  const float* __restrict__ trans,
                  float* __restrict__ d_out,
                  int n_leaves)
{
    __shared__ __align__(16) float s1[32 * LBL];
    __shared__ __align__(16) float s2[16 * LBL];
    __shared__ __align__(16) float stg[WPB][4 * LBL];

    int lane = threadIdx.x & 31;
    int w    = threadIdx.x >> 5;
    unsigned nblocks = gridDim.x;
    unsigned myphase = *(volatile unsigned*)&g_bar_phase;

    u64 rT2[16];
    load_expT2(rT2, trans, lane);

    float* bufs[4] = { g_A, g_B, g_C, g_D };
    const float* child = emissions + (size_t)(n_leaves - 1) * LBL;  // leaves

    int V = n_leaves / 2;
    int bi = 0;
    while (V >= 128) {
        float* out = bufs[bi++];
        const float* em1 = emissions + (size_t)(V - 1) * LBL;
        const float* em2 = emissions + (size_t)(V / 2 - 1) * LBL;
        const float* em3 = emissions + (size_t)(V / 4 - 1) * LBL;
        int nslabs = V / 32;

        for (int s = blockIdx.x; s < nslabs; s += nblocks) {
            // ---- Stage 1: 32 nodes at level V, 2 pairs per warp, with
            //      depth-1 prefetch of the next pair's 6 loads.
            int n0 = 0 * WPB + w, n1 = 1 * WPB + w;   // pair 0
            float lv0 = child[(size_t)(2 * (s * 32 + n0)) * LBL + lane];
            float rv0 = child[(size_t)(2 * (s * 32 + n0)) * LBL + LBL + lane];
            float ev0 = em1[(size_t)(s * 32 + n0) * LBL + lane];
            float lv1 = child[(size_t)(2 * (s * 32 + n1)) * LBL + lane];
            float rv1 = child[(size_t)(2 * (s * 32 + n1)) * LBL + LBL + lane];
            float ev1 = em1[(size_t)(s * 32 + n1) * LBL + lane];
            #pragma unroll
            for (int t = 0; t < 2; t++) {
                float lv2, rv2, ev2, lv3, rv3, ev3;
                if (t == 0) {
                    int m0 = 2 * WPB + w, m1 = 3 * WPB + w;   // pair 1
                    lv2 = child[(size_t)(2 * (s * 32 + m0)) * LBL + lane];
                    rv2 = child[(size_t)(2 * (s * 32 + m0)) * LBL + LBL + lane];
                    ev2 = em1[(size_t)(s * 32 + m0) * LBL + lane];
                    lv3 = child[(size_t)(2 * (s * 32 + m1)) * LBL + lane];
                    rv3 = child[(size_t)(2 * (s * 32 + m1)) * LBL + LBL + lane];
                    ev3 = em1[(size_t)(s * 32 + m1) * LBL + lane];
                }
                float r0, r1;
                node_pair(lv0, rv0, ev0, lv1, rv1, ev1, lane, stg[w], rT2, r0, r1);
                int a0 = (2 * t) * WPB + w, a1 = (2 * t + 1) * WPB + w;
                s1[a0 * LBL + lane] = r0;
                s1[a1 * LBL + lane] = r1;
                lv0 = lv2; rv0 = rv2; ev0 = ev2;
                lv1 = lv3; rv1 = rv3; ev1 = ev3;
            }
            __syncthreads();

            // ---- Stage 2: 16 nodes at level V/2 (one pair per warp).
            {
                int a0 = w, a1 = WPB + w;
                float lv0s = s1[2 * a0 * LBL + lane];
                float rv0s = s1[2 * a0 * LBL + LBL + lane];
                float ev0s = em2[(size_t)(s * 16 + a0) * LBL + lane];
                float lv1s = s1[2 * a1 * LBL + lane];
                float rv1s = s1[2 * a1 * LBL + LBL + lane];
                float ev1s = em2[(size_t)(s * 16 + a1) * LBL + lane];
                float r0, r1;
                node_pair(lv0s, rv0s, ev0s, lv1s, rv1s, ev1s, lane, stg[w], rT2, r0, r1);
                s2[a0 * LBL + lane] = r0;
                s2[a1 * LBL + lane] = r1;
            }
            __syncthreads();

            // ---- Stage 3: 8 nodes at level V/4, children in s2 -> global.
            {
                int n = w;
                float lvs = s2[2 * n * LBL + lane];
                float rvs = s2[2 * n * LBL + LBL + lane];
                float evs = em3[(size_t)(s * 8 + n) * LBL + lane];
                float r = node_core(lvs, rvs, evs, lane, stg[w], rT2);
                out[(size_t)(s * 8 + n) * LBL + lane] = r;
            }
            __syncthreads();   // s1/s2 reuse safety for next slab
        }

        grid_barrier(nblocks, myphase);
        child = out;
        V >>= 3;
    }

    // ---- Tail: remaining levels (V=16..1), block 0 only.
    if (blockIdx.x == 0) {
        const float* c = child;
        float* o = s1;
        for (int v = V; v >= 1; v >>= 1) {
            const float* em = emissions + (size_t)(v - 1) * LBL;
            for (int n = w; n < v; n += WPB) {
                float lvs = c[(size_t)(2 * n) * LBL + lane];
                float rvs = c[(size_t)(2 * n) * LBL + LBL + lane];
                float evs = em[(size_t)n * LBL + lane];
                float r = node_core(lvs, rvs, evs, lane, stg[w], rT2);
                if (v > 1) o[n * LBL + lane] = r;
                else       d_out[lane] = r;
            }
            __syncthreads();
            c = o;
            o = (o == s1) ? s2 : s1;   // v<=16 fits in s2 (16 rows)
        }
    }
}

// ---------------------------------------------------------------------------
// One graph node. Grid sized so ALL blocks are simultaneously resident
// (required by the software grid barrier).
// ---------------------------------------------------------------------------
extern "C" void kernel_launch(void* const* d_in, const int* in_sizes, int n_in,
                              void* d_out, int out_size)
{
    const float* emissions = (const float*)d_in[0];
    const float* trans     = (const float*)d_in[1];
    float* out = (float*)d_out;

    int n_nodes  = in_sizes[0] / LBL;
    int n_leaves = (n_nodes + 1) / 2;

    static int grid = 0;
    if (grid == 0) {
        int dev = 0, sms = 0, perSM = 0;
        cudaGetDevice(&dev);
        cudaDeviceGetAttribute(&sms, cudaDevAttrMultiProcessorCount, dev);
        cudaOccupancyMaxActiveBlocksPerMultiprocessor(
            &perSM, persistent_kernel, WPB * 32, 0);
        if (perSM < 1) perSM = 1;
        grid = sms * perSM;
        int maxSlabs = (n_leaves / 2) / 32;
        if (grid > maxSlabs) grid = maxSlabs;
        if (grid < 1) grid = 1;
    }

    persistent_kernel<<<grid, WPB * 32>>>(emissions, trans, out, n_leaves);
}